// round 2
// baseline (speedup 1.0000x reference)
#include <cuda_runtime.h>

// ---------------------------------------------------------------------------
// WideHyperBasicBlock: B=32, C=256, H=W=64, HD=1
// h_b = 0.5 + h_in[b]/64 (scalar) => per-sample conv weight = h_b*W + Bw
// Pipeline:
//   act1 = relu(bn1(x))                      [elementwise kernel]
//   act2 = relu(bn2(conv3x3(act1, h*W1+B1))) [conv kernel, MODE 0 epilogue]
//   out  = conv3x3(act2, h*W2+B2) + x        [conv kernel, MODE 1 epilogue]
// ---------------------------------------------------------------------------

#define NB   32
#define NC   256
#define NH   64
#define NW   64
#define HWSZ (NH * NW)          // 4096
#define TOTAL (NB * NC * HWSZ)  // 33554432

// scratch (allocation-free: __device__ globals)
__device__ float g_act1[TOTAL];
__device__ float g_act2[TOTAL];

// ---------------------------------------------------------------------------
__global__ void bn_relu_kernel(const float* __restrict__ x,
                               const float* __restrict__ gamma,
                               const float* __restrict__ beta,
                               const float* __restrict__ mean,
                               const float* __restrict__ var,
                               float* __restrict__ out)
{
    int idx = blockIdx.x * blockDim.x + threadIdx.x;
    int c = (idx >> 12) & (NC - 1);
    float inv  = gamma[c] * rsqrtf(var[c] + 1e-5f);
    float bias = beta[c] - mean[c] * inv;
    float v = fmaf(x[idx], inv, bias);
    out[idx] = fmaxf(v, 0.0f);
}

// ---------------------------------------------------------------------------
// Conv: 3x3 SAME, 256->256, per-sample weight = h_b*wmat + wbias.
// Block: 64 output channels x 16x16 spatial tile for one sample.
// Thread: 8 co x 8 px accumulators.
// MODE 0: epilogue relu(bn2(v))   -> out
// MODE 1: epilogue v + xres       -> out
// ---------------------------------------------------------------------------
template <int MODE>
__global__ __launch_bounds__(256)
void conv_kernel(const float* __restrict__ in,
                 const float* __restrict__ wmat,
                 const float* __restrict__ wbias,
                 const float* __restrict__ hvec,
                 const float* __restrict__ bn_g,
                 const float* __restrict__ bn_b,
                 const float* __restrict__ bn_m,
                 const float* __restrict__ bn_v,
                 const float* __restrict__ xres,
                 float* __restrict__ out)
{
    __shared__ float s_in[8][324];     // 8 ci x 18x18 halo tile
    __shared__ float s_w[9][8][64];    // k x ci x co (combined weights)

    const int tid   = threadIdx.x;
    const int tileY = (blockIdx.x >> 2) * 16;
    const int tileX = (blockIdx.x & 3) * 16;
    const int co0   = blockIdx.y * 64;
    const int b     = blockIdx.z;

    const float h = 0.5f + hvec[b] * (1.0f / 64.0f);

    const int r   = tid >> 4;               // 0..15 pixel row in tile
    const int xh  = ((tid >> 3) & 1) * 8;   // 0 or 8 (x half)
    const int cot = (tid & 7) * 8;          // 0..56 (co sub-offset)

    float acc[8][8];
#pragma unroll
    for (int i = 0; i < 8; i++)
#pragma unroll
        for (int j = 0; j < 8; j++) acc[i][j] = 0.0f;

    const float* inb = in + (size_t)b * NC * HWSZ;

    for (int chunk = 0; chunk < 32; chunk++) {
        // ---- stage input tile (8 ci x 18 x 18, zero-padded halo) ----
        for (int j = tid; j < 8 * 324; j += 256) {
            int ci = j / 324;
            int p  = j - ci * 324;
            int ly = p / 18;
            int lx = p - ly * 18;
            int gy = tileY + ly - 1;
            int gx = tileX + lx - 1;
            float v = 0.0f;
            if ((unsigned)gy < 64u && (unsigned)gx < 64u)
                v = inb[((chunk * 8 + ci) << 12) + (gy << 6) + gx];
            s_in[ci][p] = v;
        }
        // ---- stage combined weights: wc = h*W + Bw ----
        for (int j = tid; j < 9 * 8 * 64; j += 256) {
            int k  = j >> 9;          // /512
            int rr = j & 511;
            int ci = rr >> 6;
            int co = rr & 63;
            int widx = ((co0 + co) * NC + chunk * 8 + ci) * 9 + k;
            s_w[k][ci][co] = fmaf(h, wmat[widx], wbias[widx]);
        }
        __syncthreads();

        // ---- compute ----
#pragma unroll
        for (int ci = 0; ci < 8; ci++) {
            float rows[3][10];
#pragma unroll
            for (int ky = 0; ky < 3; ky++)
#pragma unroll
                for (int j = 0; j < 10; j++)
                    rows[ky][j] = s_in[ci][(r + ky) * 18 + xh + j];

#pragma unroll
            for (int ky = 0; ky < 3; ky++) {
#pragma unroll
                for (int kx = 0; kx < 3; kx++) {
                    const float4 wa = *(const float4*)&s_w[ky * 3 + kx][ci][cot];
                    const float4 wb = *(const float4*)&s_w[ky * 3 + kx][ci][cot + 4];
                    float wv[8] = {wa.x, wa.y, wa.z, wa.w, wb.x, wb.y, wb.z, wb.w};
#pragma unroll
                    for (int i = 0; i < 8; i++)
#pragma unroll
                        for (int j = 0; j < 8; j++)
                            acc[i][j] = fmaf(wv[i], rows[ky][kx + j], acc[i][j]);
                }
            }
        }
        __syncthreads();
    }

    // ---- epilogue ----
    const int y  = tileY + r;
    const int x0 = tileX + xh;
#pragma unroll
    for (int i = 0; i < 8; i++) {
        const int co = co0 + cot + i;
        size_t base = (((size_t)b * NC + co) << 12) + (y << 6) + x0;
        if (MODE == 0) {
            float inv  = bn_g[co] * rsqrtf(bn_v[co] + 1e-5f);
            float bias = bn_b[co] - bn_m[co] * inv;
#pragma unroll
            for (int j = 0; j < 8; j++)
                out[base + j] = fmaxf(fmaf(acc[i][j], inv, bias), 0.0f);
        } else {
#pragma unroll
            for (int j = 0; j < 8; j++)
                out[base + j] = acc[i][j] + xres[base + j];
        }
    }
}

// ---------------------------------------------------------------------------
extern "C" void kernel_launch(void* const* d_in, const int* in_sizes, int n_in,
                              void* d_out, int out_size)
{
    const float* x    = (const float*)d_in[0];
    const float* h_in = (const float*)d_in[1];
    const float* g1   = (const float*)d_in[2];
    const float* be1  = (const float*)d_in[3];
    const float* m1   = (const float*)d_in[4];
    const float* v1   = (const float*)d_in[5];
    const float* w1   = (const float*)d_in[6];
    const float* b1   = (const float*)d_in[7];
    const float* g2   = (const float*)d_in[8];
    const float* be2  = (const float*)d_in[9];
    const float* m2   = (const float*)d_in[10];
    const float* v2   = (const float*)d_in[11];
    const float* w2   = (const float*)d_in[12];
    const float* b2   = (const float*)d_in[13];
    float* out = (float*)d_out;

    float *act1, *act2;
    cudaGetSymbolAddress((void**)&act1, g_act1);
    cudaGetSymbolAddress((void**)&act2, g_act2);

    // 1) act1 = relu(bn1(x))
    bn_relu_kernel<<<TOTAL / 256, 256>>>(x, g1, be1, m1, v1, act1);

    // 2) act2 = relu(bn2(conv(act1, h*W1+B1)))   [FIX: pass be2, not b2]
    dim3 grid(16, 4, NB);
    conv_kernel<0><<<grid, 256>>>(act1, w1, b1, h_in, g2, be2, m2, v2,
                                  nullptr, act2);

    // 3) out = conv(act2, h*W2+B2) + x
    conv_kernel<1><<<grid, 256>>>(act2, w2, b2, h_in, nullptr, nullptr,
                                  nullptr, nullptr, x, out);
}

// round 4
// speedup vs baseline: 8.1055x; 8.1055x over previous
#include <cuda_runtime.h>
#include <cuda_fp16.h>
#include <cstdint>

// ---------------------------------------------------------------------------
// WideHyperBasicBlock via mma.sync (HMMA, base sm_103 ISA — tcgen05 is
// 'a'-gated and the harness targets plain sm_103).
// conv3x3 = 9 shifted GEMMs, fp16 in / fp32 accum.
// act padded [b][c][66][72] fp16, 3 x-shifted copies (16B-aligned rows).
// combined weights h_b*W+Bw precomputed fp16 [b][tap][co][ci].
// ---------------------------------------------------------------------------

#define NB 32
#define NC 256
#define PROW 66
#define PCOLS 72
#define PSZ (NB * NC * PROW * PCOLS)
#define GWSZ (NB * 9 * NC * NC)

__device__ __half g_actp1[3][PSZ];
__device__ __half g_actp2[3][PSZ];
__device__ __half g_gw1[GWSZ];
__device__ __half g_gw2[GWSZ];

__device__ __forceinline__ uint32_t smem_u32(const void* p) {
    uint32_t a;
    asm("{ .reg .u64 t; cvta.to.shared.u64 t, %1; cvt.u32.u64 %0, t; }"
        : "=r"(a) : "l"(p));
    return a;
}
#define SWZ(o) ((o) ^ (((o) >> 3) & 0x70))
#define CPA16(dst, src) \
    asm volatile("cp.async.cg.shared.global [%0], [%1], 16;" :: "r"(dst), "l"(src) : "memory")

// --------------------------- aux kernels -----------------------------------
__global__ void zero_borders(__half* buf) {
    int t = blockIdx.x * blockDim.x + threadIdx.x;
    if (t >= 3 * NB * NC) return;
    int copy = t / (NB * NC);
    int bc   = t % (NB * NC);
    __half* base = buf + (size_t)copy * PSZ + (size_t)bc * PROW * PCOLS;
    uint4 z = {0, 0, 0, 0};
#pragma unroll
    for (int g = 0; g < 9; g++) {
        ((uint4*)(base))[g] = z;
        ((uint4*)(base + 65 * PCOLS))[g] = z;
    }
    __half hz = __float2half(0.0f);
    if (copy == 0) for (int r = 1; r < 65; r++) base[r * PCOLS] = hz;
    if (copy == 2) for (int r = 1; r < 65; r++) base[r * PCOLS + 63] = hz;
}

__global__ void wcombine(const float* __restrict__ w, const float* __restrict__ bw,
                         const float* __restrict__ hv, __half* __restrict__ gw) {
    int idx = blockIdx.x * blockDim.x + threadIdx.x;   // [b][k][co][ci]
    int ci = idx & 255, co = (idx >> 8) & 255;
    int bk = idx >> 16;
    int k = bk % 9, b = bk / 9;
    float h = 0.5f + hv[b] * (1.0f / 64.0f);
    int widx = (co * 256 + ci) * 9 + k;
    gw[idx] = __float2half(fmaf(h, w[widx], bw[widx]));
}

__global__ void bn_relu_pad(const float* __restrict__ x,
                            const float* __restrict__ g, const float* __restrict__ be,
                            const float* __restrict__ m, const float* __restrict__ v,
                            __half* __restrict__ a0, __half* __restrict__ a1,
                            __half* __restrict__ a2) {
    int idx = blockIdx.x * blockDim.x + threadIdx.x;
    int c = (idx >> 12) & 255;
    int p = idx & 4095;
    int b = idx >> 20;
    int yy = p >> 6, xx = p & 63;
    float inv  = g[c] * rsqrtf(v[c] + 1e-5f);
    float bias = be[c] - m[c] * inv;
    __half h = __float2half(fmaxf(fmaf(x[idx], inv, bias), 0.0f));
    int rb = ((b * 256 + c) * PROW + yy + 1) * PCOLS;
    a0[rb + xx + 1] = h;
    a1[rb + xx] = h;
    if (xx >= 1) a2[rb + xx - 1] = h;
}

// --------------------------- main conv kernel ------------------------------
// CTA: 128 co x 128 px (2 image rows) for one sample. 256 threads, 8 warps.
// Warp tile: 64 co x 32 px.  K loop: 36 stages (9 taps x 4 ci-chunks of 64).
// SMEM: A[2][128co x 64ci] fp16 @0/16384; B[2][2blk x 64ci x 64px] @32768/49152.
#define SMEM_BYTES 65536

template <int MODE>
__global__ __launch_bounds__(256)
void conv_mma(const __half* __restrict__ ap0, const __half* __restrict__ ap1,
              const __half* __restrict__ ap2, const __half* __restrict__ gw,
              const float* __restrict__ bn_g, const float* __restrict__ bn_b,
              const float* __restrict__ bn_m, const float* __restrict__ bn_v,
              const float* __restrict__ xres,
              __half* __restrict__ o0, __half* __restrict__ o1, __half* __restrict__ o2,
              float* __restrict__ out)
{
    extern __shared__ __align__(1024) char smem[];
    const uint32_t sb = smem_u32(smem);
    const int tid  = threadIdx.x;
    const int wid  = tid >> 5, lane = tid & 31;
    const int wm   = wid & 1;          // co half within CTA tile
    const int wn   = wid >> 1;         // 0..3: 32-px column strip
    const int jblk = wn >> 1;          // which 64-px B block
    const int nbase = (wn & 1) * 32;   // px offset within block

    const int y0  = blockIdx.x * 2;    // first output row of CTA
    const int co0 = blockIdx.y * 128;
    const int b   = blockIdx.z;

    const int lr  = lane & 15;
    const int lhi = (lane >> 4) & 1;

    float acc[4][4][4];
#pragma unroll
    for (int i = 0; i < 4; i++)
#pragma unroll
        for (int j = 0; j < 4; j++)
#pragma unroll
            for (int k = 0; k < 4; k++) acc[i][j][k] = 0.0f;

    auto stage_load = [&](int s) {
        const int buf = s & 1;
        const int tap = s >> 2;
        const int cic = (s & 3) << 6;
        const int ky  = tap / 3;
        const int kx  = tap - ky * 3;
        const __half* ap = (kx == 0) ? ap0 : (kx == 1) ? ap1 : ap2;
        const uint32_t sA = sb + buf * 16384;
        const uint32_t sB = sb + 32768 + buf * 16384;
        const __half* gsrcA = gw + ((size_t)(b * 9 + tap) * 256 + co0) * 256 + cic;
        for (int i = tid; i < 2048; i += 256) {
            if (i < 1024) {                       // A: [128 co][64 ci]
                int row = i >> 3, g = i & 7;
                CPA16(sA + SWZ(row * 128 + g * 16),
                      (const char*)(gsrcA + row * 256) + g * 16);
            } else {                              // B: 2 blk x [64 ci][64 px]
                int idx = i - 1024;
                int j = idx >> 9, r = (idx >> 3) & 63, g = idx & 7;
                CPA16(sB + j * 8192 + SWZ(r * 128 + g * 16),
                      (const char*)(ap + ((size_t)(b * 256 + cic + r) * PROW +
                                          (y0 + j + ky)) * PCOLS) + g * 16);
            }
        }
        asm volatile("cp.async.commit_group;" ::: "memory");
    };

    stage_load(0);
    stage_load(1);

    for (int s = 0; s < 36; s++) {
        const int buf = s & 1;
        asm volatile("cp.async.wait_group 1;" ::: "memory");
        __syncthreads();

        const uint32_t sA  = sb + buf * 16384;
        const uint32_t sBj = sb + 32768 + buf * 16384 + jblk * 8192;

#pragma unroll
        for (int ki = 0; ki < 4; ki++) {
            uint32_t a[4][4];
#pragma unroll
            for (int mi = 0; mi < 4; mi++) {
                uint32_t addr = sA + SWZ((wm * 64 + mi * 16 + lr) * 128 +
                                         ki * 32 + lhi * 16);
                asm volatile("ldmatrix.sync.aligned.m8n8.x4.shared.b16 {%0,%1,%2,%3}, [%4];"
                             : "=r"(a[mi][0]), "=r"(a[mi][1]), "=r"(a[mi][2]), "=r"(a[mi][3])
                             : "r"(addr));
            }
            uint32_t bm[2][4];
#pragma unroll
            for (int nt = 0; nt < 2; nt++) {
                uint32_t addr = sBj + SWZ((ki * 16 + lr) * 128 +
                                          (nbase + nt * 16 + lhi * 8) * 2);
                asm volatile("ldmatrix.sync.aligned.m8n8.x4.trans.shared.b16 {%0,%1,%2,%3}, [%4];"
                             : "=r"(bm[nt][0]), "=r"(bm[nt][1]), "=r"(bm[nt][2]), "=r"(bm[nt][3])
                             : "r"(addr));
            }
#pragma unroll
            for (int mi = 0; mi < 4; mi++)
#pragma unroll
                for (int ni = 0; ni < 4; ni++) {
                    uint32_t b0 = bm[ni >> 1][(ni & 1) * 2];
                    uint32_t b1 = bm[ni >> 1][(ni & 1) * 2 + 1];
                    asm volatile(
                        "mma.sync.aligned.m16n8k16.row.col.f32.f16.f16.f32 "
                        "{%0,%1,%2,%3}, {%4,%5,%6,%7}, {%8,%9}, {%0,%1,%2,%3};"
                        : "+f"(acc[mi][ni][0]), "+f"(acc[mi][ni][1]),
                          "+f"(acc[mi][ni][2]), "+f"(acc[mi][ni][3])
                        : "r"(a[mi][0]), "r"(a[mi][1]), "r"(a[mi][2]), "r"(a[mi][3]),
                          "r"(b0), "r"(b1));
                }
        }
        __syncthreads();
        if (s + 2 < 36) stage_load(s + 2);
        else asm volatile("cp.async.commit_group;" ::: "memory");
    }

    // ---- epilogue ----
#pragma unroll
    for (int mi = 0; mi < 4; mi++) {
#pragma unroll
        for (int h = 0; h < 2; h++) {
            const int co = co0 + wm * 64 + mi * 16 + (lane >> 2) + h * 8;
            float inv = 0.0f, bias = 0.0f;
            if (MODE == 0) {
                inv  = bn_g[co] * rsqrtf(bn_v[co] + 1e-5f);
                bias = bn_b[co] - bn_m[co] * inv;
            }
#pragma unroll
            for (int ni = 0; ni < 4; ni++) {
                const int px  = wn * 32 + ni * 8 + (lane & 3) * 2;
                const int row = y0 + (px >> 6);
                const int x0  = px & 63;
                const float v0 = acc[mi][ni][h * 2];
                const float v1 = acc[mi][ni][h * 2 + 1];
                if (MODE == 0) {
                    __half h0 = __float2half(fmaxf(fmaf(v0, inv, bias), 0.0f));
                    __half h1 = __float2half(fmaxf(fmaf(v1, inv, bias), 0.0f));
                    const int rb = ((b * 256 + co) * PROW + row + 1) * PCOLS;
                    *(__half2*)(o1 + rb + x0) = __halves2half2(h0, h1);
                    o0[rb + x0 + 1] = h0;
                    o0[rb + x0 + 2] = h1;
                    if (x0 >= 1) o2[rb + x0 - 1] = h0;
                    o2[rb + x0] = h1;
                } else {
                    const int gb = ((b * 256 + co) << 12) + (row << 6) + x0;
                    float2 xr = *(const float2*)(xres + gb);
                    float2 o;
                    o.x = v0 + xr.x;
                    o.y = v1 + xr.y;
                    *(float2*)(out + gb) = o;
                }
            }
        }
    }
}

// ------------------------------- launcher ----------------------------------
extern "C" void kernel_launch(void* const* d_in, const int* in_sizes, int n_in,
                              void* d_out, int out_size)
{
    const float* x    = (const float*)d_in[0];
    const float* h_in = (const float*)d_in[1];
    const float* g1   = (const float*)d_in[2];
    const float* be1  = (const float*)d_in[3];
    const float* m1   = (const float*)d_in[4];
    const float* v1   = (const float*)d_in[5];
    const float* w1   = (const float*)d_in[6];
    const float* b1   = (const float*)d_in[7];
    const float* g2   = (const float*)d_in[8];
    const float* be2  = (const float*)d_in[9];
    const float* m2   = (const float*)d_in[10];
    const float* v2   = (const float*)d_in[11];
    const float* w2   = (const float*)d_in[12];
    const float* b2   = (const float*)d_in[13];
    float* out = (float*)d_out;

    void *p1, *p2, *pg1, *pg2;
    cudaGetSymbolAddress(&p1, g_actp1);
    cudaGetSymbolAddress(&p2, g_actp2);
    cudaGetSymbolAddress(&pg1, g_gw1);
    cudaGetSymbolAddress(&pg2, g_gw2);
    __half* ap1 = (__half*)p1;
    __half* ap2 = (__half*)p2;
    __half* gw1 = (__half*)pg1;
    __half* gw2 = (__half*)pg2;

    cudaFuncSetAttribute(conv_mma<0>, cudaFuncAttributeMaxDynamicSharedMemorySize, SMEM_BYTES);
    cudaFuncSetAttribute(conv_mma<1>, cudaFuncAttributeMaxDynamicSharedMemorySize, SMEM_BYTES);

    zero_borders<<<(3 * NB * NC + 255) / 256, 256>>>(ap1);
    zero_borders<<<(3 * NB * NC + 255) / 256, 256>>>(ap2);
    wcombine<<<GWSZ / 256, 256>>>(w1, b1, h_in, gw1);
    wcombine<<<GWSZ / 256, 256>>>(w2, b2, h_in, gw2);
    bn_relu_pad<<<(NB * NC * 4096) / 256, 256>>>(x, g1, be1, m1, v1,
                                                 ap1, ap1 + PSZ, ap1 + 2 * (size_t)PSZ);

    dim3 cg(32, 2, NB);
    conv_mma<0><<<cg, 256, SMEM_BYTES>>>(ap1, ap1 + PSZ, ap1 + 2 * (size_t)PSZ, gw1,
                                         g2, be2, m2, v2, nullptr,
                                         ap2, ap2 + PSZ, ap2 + 2 * (size_t)PSZ, nullptr);
    conv_mma<1><<<cg, 256, SMEM_BYTES>>>(ap2, ap2 + PSZ, ap2 + 2 * (size_t)PSZ, gw2,
                                         nullptr, nullptr, nullptr, nullptr, x,
                                         nullptr, nullptr, nullptr, out);
}